// round 2
// baseline (speedup 1.0000x reference)
#include <cuda_runtime.h>
#include <cstddef>

// ---------------------------------------------------------------------------
// RWKV TimeMixing: B=8, T=2048, C=1024
//   xx = shift(x);  xk/xv/xr = mix(x, xx)
//   k = xk@Wk; v = xv@Wv; r = xr@Wr
//   wkv = serial scan over T (log-sum-exp linear recurrence)
//   out = (sigmoid(r)*wkv) @ Wo
// Outputs (concatenated fp32): out[B,T,C], x[:,-1,:], aa, bb, pp
// ---------------------------------------------------------------------------

constexpr int B_ = 8;
constexpr int T_ = 2048;
constexpr int C_ = 1024;
constexpr int M_ = B_ * T_;                 // 16384 rows
constexpr size_t BTC_ = (size_t)M_ * C_;    // 16,777,216
constexpr int BC_ = B_ * C_;                // 8192
constexpr int C4_ = C_ / 4;

// Scratch (device globals; no runtime allocation allowed)
__device__ float g_xk[BTC_];
__device__ float g_xv[BTC_];
__device__ float g_xr[BTC_];
__device__ float g_k[BTC_];
__device__ float g_v[BTC_];
__device__ float g_r[BTC_];
// rw = sigmoid(r)*wkv reuses g_xk (xk is dead after the k-GEMM, which
// completes before the scan writes rw — stream-ordered).

// ---------------------------------------------------------------------------
// 1) Token-shift + time-mix (vectorized float4), also emits last_x output
// ---------------------------------------------------------------------------
__device__ __forceinline__ float4 mix4(float4 a, float4 xx, float4 m) {
    // a*m + xx*(1-m) = xx + m*(a-xx)
    float4 r;
    r.x = fmaf(m.x, a.x - xx.x, xx.x);
    r.y = fmaf(m.y, a.y - xx.y, xx.y);
    r.z = fmaf(m.z, a.z - xx.z, xx.z);
    r.w = fmaf(m.w, a.w - xx.w, xx.w);
    return r;
}

__global__ void mix_kernel(const float4* __restrict__ x,
                           const float4* __restrict__ last_x,
                           const float4* __restrict__ tmk,
                           const float4* __restrict__ tmv,
                           const float4* __restrict__ tmr,
                           float4* __restrict__ xk,
                           float4* __restrict__ xv,
                           float4* __restrict__ xr,
                           float4* lastx_out) {
    size_t i = (size_t)blockIdx.x * blockDim.x + threadIdx.x;
    if (i >= BTC_ / 4) return;
    int c4 = (int)(i % C4_);
    size_t bt = i / C4_;
    int t = (int)(bt % T_);
    int b = (int)(bt / T_);

    float4 xc = x[i];
    float4 xx = (t == 0) ? last_x[(size_t)b * C4_ + c4] : x[i - C4_];
    float4 mk = tmk[c4];
    float4 mv = tmv[c4];
    float4 mr = tmr[c4];

    xk[i] = mix4(xc, xx, mk);
    xv[i] = mix4(xc, xx, mv);
    xr[i] = mix4(xc, xx, mr);

    if (t == T_ - 1 && lastx_out) lastx_out[(size_t)b * C4_ + c4] = xc;
}

// ---------------------------------------------------------------------------
// 2) SGEMM: C[M,N] = A[M,K] @ W[K,N], fp32, K=N=1024.
//    128x128 block, BK=16, 256 threads, 8x8 per-thread tile, double-buffered.
// ---------------------------------------------------------------------------
__global__ __launch_bounds__(256, 2) void sgemm_kernel(
    const float* __restrict__ A, const float* __restrict__ Bw,
    float* __restrict__ Cout) {
    constexpr int K = C_;
    constexpr int N = C_;
    constexpr int BM = 128, BN = 128, BK = 16;
    constexpr int NT = K / BK;  // 64 k-tiles

    __shared__ float As[2][BK][BM];
    __shared__ float Bs[2][BK][BN];

    const int tid = threadIdx.x;
    const int bm = blockIdx.y * BM;
    const int bn = blockIdx.x * BN;

    // A-tile load map: 2 x float4 per thread (BM x BK transposed into As)
    const int arow = tid >> 2;          // 0..63
    const int acol = (tid & 3) << 2;    // 0,4,8,12
    // B-tile load map: 2 x float4 per thread (BK x BN)
    const int brow = tid >> 5;          // 0..7
    const int bcol = (tid & 31) << 2;   // 0..124

    const float* Ab = A + (size_t)bm * K;
    const float* Bb = Bw + bn;

    const int tx = tid & 15;  // 0..15  -> 8 output cols
    const int ty = tid >> 4;  // 0..15  -> 8 output rows

    float acc[8][8];
#pragma unroll
    for (int i = 0; i < 8; i++)
#pragma unroll
        for (int j = 0; j < 8; j++) acc[i][j] = 0.0f;

    auto load_tile = [&](int kt, int buf) {
#pragma unroll
        for (int i = 0; i < 2; i++) {
            const int r = arow + i * 64;
            const float4 va = *reinterpret_cast<const float4*>(
                Ab + (size_t)r * K + kt + acol);
            As[buf][acol + 0][r] = va.x;
            As[buf][acol + 1][r] = va.y;
            As[buf][acol + 2][r] = va.z;
            As[buf][acol + 3][r] = va.w;
        }
#pragma unroll
        for (int i = 0; i < 2; i++) {
            const int r = brow + i * 8;
            *reinterpret_cast<float4*>(&Bs[buf][r][bcol]) =
                *reinterpret_cast<const float4*>(Bb + (size_t)(kt + r) * N + bcol);
        }
    };

    load_tile(0, 0);
    __syncthreads();

    for (int t = 0; t < NT; t++) {
        if (t + 1 < NT) load_tile((t + 1) * BK, (t + 1) & 1);
        const int buf = t & 1;
#pragma unroll
        for (int k = 0; k < BK; k++) {
            float ra[8], rb[8];
            *reinterpret_cast<float4*>(&ra[0]) =
                *reinterpret_cast<const float4*>(&As[buf][k][ty * 8]);
            *reinterpret_cast<float4*>(&ra[4]) =
                *reinterpret_cast<const float4*>(&As[buf][k][ty * 8 + 4]);
            *reinterpret_cast<float4*>(&rb[0]) =
                *reinterpret_cast<const float4*>(&Bs[buf][k][tx * 8]);
            *reinterpret_cast<float4*>(&rb[4]) =
                *reinterpret_cast<const float4*>(&Bs[buf][k][tx * 8 + 4]);
#pragma unroll
            for (int i = 0; i < 8; i++)
#pragma unroll
                for (int j = 0; j < 8; j++)
                    acc[i][j] = fmaf(ra[i], rb[j], acc[i][j]);
        }
        __syncthreads();
    }

#pragma unroll
    for (int i = 0; i < 8; i++) {
        float* cr = Cout + (size_t)(bm + ty * 8 + i) * N + bn + tx * 8;
        *reinterpret_cast<float4*>(cr) =
            make_float4(acc[i][0], acc[i][1], acc[i][2], acc[i][3]);
        *reinterpret_cast<float4*>(cr + 4) =
            make_float4(acc[i][4], acc[i][5], acc[i][6], acc[i][7]);
    }
}

// ---------------------------------------------------------------------------
// 3) WKV serial scan over T, fused with sigmoid(r)*wkv.
//    One thread per (b, c) lane. Coalesced across c.
// ---------------------------------------------------------------------------
__global__ void wkv_kernel(const float* __restrict__ k,
                           const float* __restrict__ v,
                           const float* __restrict__ r,
                           const float* __restrict__ aa0,
                           const float* __restrict__ bb0,
                           const float* __restrict__ pp0,
                           const float* __restrict__ tf,
                           const float* __restrict__ td,
                           float* __restrict__ rw,
                           float* aa_out, float* bb_out, float* pp_out) {
    const int idx = blockIdx.x * blockDim.x + threadIdx.x;
    if (idx >= BC_) return;
    const int c = idx & (C_ - 1);

    float aa = aa0[idx];
    float bb = bb0[idx];
    float pp = pp0[idx];
    const float u = tf[c];
    const float w = td[c];

    const size_t base = (size_t)(idx >> 10) * (size_t)T_ * C_ + c;

    for (int t = 0; t < T_; t++) {
        const size_t off = base + (size_t)t * C_;
        const float kt = k[off];
        const float vt = v[off];

        const float ww = u + kt;
        const float qq = fmaxf(pp, ww);
        const float e1 = __expf(pp - qq);
        const float e2 = __expf(ww - qq);
        const float wkv = fmaf(e1, aa, e2 * vt) / fmaf(e1, bb, e2);

        const float rt = r[off];
        const float sig = 1.0f / (1.0f + __expf(-rt));
        rw[off] = sig * wkv;

        const float ww2 = pp + w;
        const float qq2 = fmaxf(ww2, kt);
        const float e1b = __expf(ww2 - qq2);
        const float e2b = __expf(kt - qq2);
        aa = fmaf(e1b, aa, e2b * vt);
        bb = fmaf(e1b, bb, e2b);
        pp = qq2;
    }

    if (aa_out) {
        aa_out[idx] = aa;
        bb_out[idx] = bb;
        pp_out[idx] = pp;
    }
}

// ---------------------------------------------------------------------------
// Launch
// ---------------------------------------------------------------------------
extern "C" void kernel_launch(void* const* d_in, const int* in_sizes, int n_in,
                              void* d_out, int out_size) {
    const float* x   = (const float*)d_in[0];
    const float* lx  = (const float*)d_in[1];
    const float* aa0 = (const float*)d_in[2];
    const float* bb0 = (const float*)d_in[3];
    const float* pp0 = (const float*)d_in[4];
    const float* tmk = (const float*)d_in[5];
    const float* tmv = (const float*)d_in[6];
    const float* tmr = (const float*)d_in[7];
    const float* tf  = (const float*)d_in[8];
    const float* td  = (const float*)d_in[9];
    const float* Wk  = (const float*)d_in[10];
    const float* Wv  = (const float*)d_in[11];
    const float* Wr  = (const float*)d_in[12];
    const float* Wo  = (const float*)d_in[13];

    float* out = (float*)d_out;
    const bool full = (size_t)out_size >= BTC_ + 4 * (size_t)BC_;
    float* lastx_o = full ? out + BTC_ : nullptr;
    float* aa_o    = full ? out + BTC_ + 1 * (size_t)BC_ : nullptr;
    float* bb_o    = full ? out + BTC_ + 2 * (size_t)BC_ : nullptr;
    float* pp_o    = full ? out + BTC_ + 3 * (size_t)BC_ : nullptr;

    float *xk, *xv, *xr, *kb, *vb, *rb;
    cudaGetSymbolAddress((void**)&xk, g_xk);
    cudaGetSymbolAddress((void**)&xv, g_xv);
    cudaGetSymbolAddress((void**)&xr, g_xr);
    cudaGetSymbolAddress((void**)&kb, g_k);
    cudaGetSymbolAddress((void**)&vb, g_v);
    cudaGetSymbolAddress((void**)&rb, g_r);
    float* rwb = xk;  // reuse: xk is dead after the k-GEMM

    // 1) mix (+ last_x tail output)
    {
        const size_t n4 = BTC_ / 4;
        const int threads = 256;
        const int blocks = (int)((n4 + threads - 1) / threads);
        mix_kernel<<<blocks, threads>>>(
            (const float4*)x, (const float4*)lx, (const float4*)tmk,
            (const float4*)tmv, (const float4*)tmr, (float4*)xk, (float4*)xv,
            (float4*)xr, (float4*)lastx_o);
    }

    // 2) k, v, r projections
    dim3 grid(C_ / 128, M_ / 128);  // (8, 128)
    sgemm_kernel<<<grid, 256>>>(xk, Wk, kb);
    sgemm_kernel<<<grid, 256>>>(xv, Wv, vb);
    sgemm_kernel<<<grid, 256>>>(xr, Wr, rb);

    // 3) wkv scan + sigmoid gate (writes rw and state tail outputs)
    wkv_kernel<<<BC_ / 128, 128>>>(kb, vb, rb, aa0, bb0, pp0, tf, td, rwb,
                                   aa_o, bb_o, pp_o);

    // 4) output projection
    sgemm_kernel<<<grid, 256>>>(rwb, Wo, out);
}

// round 4
// speedup vs baseline: 3.0180x; 3.0180x over previous
#include <cuda_runtime.h>
#include <cuda_bf16.h>
#include <cstdint>
#include <cstddef>

// ---------------------------------------------------------------------------
// RWKV TimeMixing B=8,T=2048,C=1024
// GEMMs: bf16 3-split (hi*hi + hi*lo + lo*hi) on mma.sync.m16n8k16 (HMMA),
// fp32 accumulate. tcgen05 unavailable: harness targets plain sm_100.
// ---------------------------------------------------------------------------
constexpr int B_ = 8;
constexpr int T_ = 2048;
constexpr int C_ = 1024;
constexpr int M_ = B_ * T_;                 // 16384
constexpr size_t BTC_ = (size_t)M_ * C_;
constexpr int BC_ = B_ * C_;
constexpr int C4_ = C_ / 4;

// Scratch (device globals; runtime allocation forbidden)
__device__ __align__(16) __nv_bfloat16 g_xk_hi[BTC_];
__device__ __align__(16) __nv_bfloat16 g_xk_lo[BTC_];
__device__ __align__(16) __nv_bfloat16 g_xv_hi[BTC_];
__device__ __align__(16) __nv_bfloat16 g_xv_lo[BTC_];
__device__ __align__(16) __nv_bfloat16 g_xr_hi[BTC_];
__device__ __align__(16) __nv_bfloat16 g_xr_lo[BTC_];
__device__ float g_k[BTC_];
__device__ float g_v[BTC_];
__device__ float g_r[BTC_];
__device__ __align__(16) __nv_bfloat16 g_wk_hi[C_ * C_];
__device__ __align__(16) __nv_bfloat16 g_wk_lo[C_ * C_];
__device__ __align__(16) __nv_bfloat16 g_wv_hi[C_ * C_];
__device__ __align__(16) __nv_bfloat16 g_wv_lo[C_ * C_];
__device__ __align__(16) __nv_bfloat16 g_wr_hi[C_ * C_];
__device__ __align__(16) __nv_bfloat16 g_wr_lo[C_ * C_];
__device__ __align__(16) __nv_bfloat16 g_wo_hi[C_ * C_];
__device__ __align__(16) __nv_bfloat16 g_wo_lo[C_ * C_];
// rw (sigmoid(r)*wkv) reuses g_xk_hi/lo — xk dead after the k-GEMM.

// ---------------------------------------------------------------------------
// PTX helpers (sm_80-era: cp.async / ldmatrix / mma.sync)
// ---------------------------------------------------------------------------
__device__ __forceinline__ uint32_t s2u(const void* p) {
    return (uint32_t)__cvta_generic_to_shared(p);
}
__device__ __forceinline__ void cp16(uint32_t s, const void* g) {
    asm volatile("cp.async.cg.shared.global [%0], [%1], 16;" :: "r"(s), "l"(g));
}
__device__ __forceinline__ void cp_commit() {
    asm volatile("cp.async.commit_group;" ::: "memory");
}
__device__ __forceinline__ void cp_wait1() {
    asm volatile("cp.async.wait_group 1;" ::: "memory");
}
__device__ __forceinline__ void ldm4(uint32_t* r, uint32_t a) {
    asm volatile("ldmatrix.sync.aligned.m8n8.x4.shared.b16 {%0,%1,%2,%3}, [%4];"
                 : "=r"(r[0]), "=r"(r[1]), "=r"(r[2]), "=r"(r[3]) : "r"(a));
}
__device__ __forceinline__ void mma16816(float* c, const uint32_t* a,
                                         uint32_t b0, uint32_t b1) {
    asm volatile(
        "mma.sync.aligned.m16n8k16.row.col.f32.bf16.bf16.f32 "
        "{%0,%1,%2,%3}, {%4,%5,%6,%7}, {%8,%9}, {%0,%1,%2,%3};"
        : "+f"(c[0]), "+f"(c[1]), "+f"(c[2]), "+f"(c[3])
        : "r"(a[0]), "r"(a[1]), "r"(a[2]), "r"(a[3]), "r"(b0), "r"(b1));
}

// Swizzled byte offset inside one 128x32-bf16 tile (rows of 64B, 16B chunks).
// Guarantees 8 distinct 16B bank-groups for any 8 consecutive rows at a fixed
// chunk (conflict-free ldmatrix) and for the cp.async store pattern.
__device__ __forceinline__ uint32_t swz(int row, int chunk) {
    return (uint32_t)(row * 64 + ((chunk ^ ((row >> 1) & 3)) << 4));
}

// ---------------------------------------------------------------------------
// 1) Weight transpose + bf16 split: W[K,N] fp32 -> Wt_hi/lo[N,K] bf16
// ---------------------------------------------------------------------------
__global__ void wt_convert_kernel(const float* __restrict__ W,
                                  __nv_bfloat16* __restrict__ hi,
                                  __nv_bfloat16* __restrict__ lo) {
    __shared__ float tile[32][33];
    const int n0 = blockIdx.x * 32, k0 = blockIdx.y * 32;
    const int tx = threadIdx.x, ty = threadIdx.y;
    for (int i = ty; i < 32; i += 8)
        tile[i][tx] = W[(size_t)(k0 + i) * C_ + n0 + tx];
    __syncthreads();
    for (int i = ty; i < 32; i += 8) {
        float w = tile[tx][i];  // = W[k0+tx][n0+i]
        __nv_bfloat16 h = __float2bfloat16(w);
        size_t o = (size_t)(n0 + i) * C_ + k0 + tx;
        hi[o] = h;
        lo[o] = __float2bfloat16(w - __bfloat162float(h));
    }
}

// ---------------------------------------------------------------------------
// 2) Token-shift + time-mix -> bf16 hi/lo operands; also last_x output
// ---------------------------------------------------------------------------
__device__ __forceinline__ float4 mix4(float4 a, float4 xx, float4 m) {
    float4 r;
    r.x = fmaf(m.x, a.x - xx.x, xx.x);
    r.y = fmaf(m.y, a.y - xx.y, xx.y);
    r.z = fmaf(m.z, a.z - xx.z, xx.z);
    r.w = fmaf(m.w, a.w - xx.w, xx.w);
    return r;
}
__device__ __forceinline__ void st_split4(float4 v, __nv_bfloat16* hi,
                                          __nv_bfloat16* lo, size_t e) {
    __nv_bfloat162 h0, h1, l0, l1;
    h0.x = __float2bfloat16(v.x); h0.y = __float2bfloat16(v.y);
    h1.x = __float2bfloat16(v.z); h1.y = __float2bfloat16(v.w);
    l0.x = __float2bfloat16(v.x - __bfloat162float(h0.x));
    l0.y = __float2bfloat16(v.y - __bfloat162float(h0.y));
    l1.x = __float2bfloat16(v.z - __bfloat162float(h1.x));
    l1.y = __float2bfloat16(v.w - __bfloat162float(h1.y));
    *reinterpret_cast<__nv_bfloat162*>(hi + e) = h0;
    *reinterpret_cast<__nv_bfloat162*>(hi + e + 2) = h1;
    *reinterpret_cast<__nv_bfloat162*>(lo + e) = l0;
    *reinterpret_cast<__nv_bfloat162*>(lo + e + 2) = l1;
}

__global__ void mix_kernel(const float4* __restrict__ x,
                           const float4* __restrict__ last_x,
                           const float4* __restrict__ tmk,
                           const float4* __restrict__ tmv,
                           const float4* __restrict__ tmr,
                           float4* lastx_out) {
    size_t i = (size_t)blockIdx.x * blockDim.x + threadIdx.x;
    if (i >= BTC_ / 4) return;
    int c4 = (int)(i % C4_);
    size_t bt = i / C4_;
    int t = (int)(bt % T_);
    int b = (int)(bt / T_);

    float4 xc = x[i];
    float4 xx = (t == 0) ? last_x[(size_t)b * C4_ + c4] : x[i - C4_];
    size_t e = i * 4;
    st_split4(mix4(xc, xx, tmk[c4]), g_xk_hi, g_xk_lo, e);
    st_split4(mix4(xc, xx, tmv[c4]), g_xv_hi, g_xv_lo, e);
    st_split4(mix4(xc, xx, tmr[c4]), g_xr_hi, g_xr_lo, e);

    if (t == T_ - 1 && lastx_out) lastx_out[(size_t)b * C4_ + c4] = xc;
}

// ---------------------------------------------------------------------------
// 3) HMMA GEMM: C[M,N] = A @ Wt^T  (A[M,K] hi/lo, Wt[N,K] hi/lo, fp32 out)
//    CTA 128x128x32, 8 warps (warp tile 32x64), 3-stage cp.async pipeline.
// ---------------------------------------------------------------------------
constexpr int BK_ = 32;
constexpr int KSTAGES = C_ / BK_;           // 32
constexpr int TILE_BYTES = 128 * BK_ * 2;   // 8192 per operand tile
constexpr int STAGE_BYTES = 4 * TILE_BYTES; // 32768 (Ah,Al,Bh,Bl)
constexpr int NSTG = 3;
constexpr int SMEM_GEMM = NSTG * STAGE_BYTES;  // 98304

__global__ __launch_bounds__(256, 1)
void gemm3_kernel(const __nv_bfloat16* __restrict__ Ah,
                  const __nv_bfloat16* __restrict__ Al,
                  const __nv_bfloat16* __restrict__ Bh,
                  const __nv_bfloat16* __restrict__ Bl,
                  float* __restrict__ Cout) {
    extern __shared__ char smem[];
    const uint32_t sbase = s2u(smem);
    const int tid = threadIdx.x;
    const int lane = tid & 31;
    const int wid = tid >> 5;
    const int wm = wid >> 1;   // 0..3  (m offset 32*wm)
    const int wn = wid & 1;    // 0..1  (n offset 64*wn)
    const int bm = blockIdx.y * 128, bn = blockIdx.x * 128;

    const char* aH = (const char*)Ah + (size_t)bm * 2048;
    const char* aL = (const char*)Al + (size_t)bm * 2048;
    const char* bH = (const char*)Bh + (size_t)bn * 2048;
    const char* bL = (const char*)Bl + (size_t)bn * 2048;

    auto load_stage = [&](int s, int buf) {
        const uint32_t sb = sbase + buf * STAGE_BYTES;
        const int kbyte = s * 64;
#pragma unroll
        for (int i = 0; i < 2; i++) {
            const int idx = tid + i * 256;  // 0..511
            const int row = idx >> 2;
            const int ch = idx & 3;
            const uint32_t so = swz(row, ch);
            const size_t go = (size_t)row * 2048 + kbyte + ch * 16;
            cp16(sb + so, aH + go);
            cp16(sb + TILE_BYTES + so, aL + go);
            cp16(sb + 2 * TILE_BYTES + so, bH + go);
            cp16(sb + 3 * TILE_BYTES + so, bL + go);
        }
        cp_commit();
    };

    float acc[2][8][4];
#pragma unroll
    for (int mt = 0; mt < 2; mt++)
#pragma unroll
        for (int nt = 0; nt < 8; nt++)
#pragma unroll
            for (int i = 0; i < 4; i++) acc[mt][nt][i] = 0.0f;

    load_stage(0, 0);
    load_stage(1, 1);

    for (int s = 0; s < KSTAGES; s++) {
        const int buf = s % NSTG;
        cp_wait1();
        __syncthreads();
        if (s + 2 < KSTAGES) load_stage(s + 2, (s + 2) % NSTG);

        const uint32_t sb = sbase + buf * STAGE_BYTES;
#pragma unroll
        for (int ks = 0; ks < 2; ks++) {
            const int lrow = lane & 15;
            const int lch = ks * 2 + (lane >> 4);
            uint32_t ahf[2][4], alf[2][4], bhf[4][4], blf[4][4];
#pragma unroll
            for (int mt = 0; mt < 2; mt++) {
                const uint32_t off = swz(wm * 32 + mt * 16 + lrow, lch);
                ldm4(ahf[mt], sb + off);
                ldm4(alf[mt], sb + TILE_BYTES + off);
            }
#pragma unroll
            for (int p = 0; p < 4; p++) {
                const uint32_t off = swz(wn * 64 + p * 16 + lrow, lch);
                ldm4(bhf[p], sb + 2 * TILE_BYTES + off);
                ldm4(blf[p], sb + 3 * TILE_BYTES + off);
            }
#pragma unroll
            for (int mt = 0; mt < 2; mt++)
#pragma unroll
                for (int p = 0; p < 4; p++) {
                    float* c0 = acc[mt][2 * p];
                    float* c1 = acc[mt][2 * p + 1];
                    mma16816(c0, ahf[mt], bhf[p][0], bhf[p][2]);
                    mma16816(c1, ahf[mt], bhf[p][1], bhf[p][3]);
                    mma16816(c0, ahf[mt], blf[p][0], blf[p][2]);
                    mma16816(c1, ahf[mt], blf[p][1], blf[p][3]);
                    mma16816(c0, alf[mt], bhf[p][0], bhf[p][2]);
                    mma16816(c1, alf[mt], bhf[p][1], bhf[p][3]);
                }
        }
        __syncthreads();
    }

    // Epilogue: direct fp32 stores (float2 per fragment half-row)
#pragma unroll
    for (int mt = 0; mt < 2; mt++) {
        const int row0 = bm + wm * 32 + mt * 16 + (lane >> 2);
#pragma unroll
        for (int nt = 0; nt < 8; nt++) {
            const int col = bn + wn * 64 + nt * 8 + (lane & 3) * 2;
            float* c = acc[mt][nt];
            *reinterpret_cast<float2*>(Cout + (size_t)row0 * C_ + col) =
                make_float2(c[0], c[1]);
            *reinterpret_cast<float2*>(Cout + (size_t)(row0 + 8) * C_ + col) =
                make_float2(c[2], c[3]);
        }
    }
}

// ---------------------------------------------------------------------------
// 4) WKV serial scan + sigmoid gate -> rw hi/lo bf16 (+ state outputs)
// ---------------------------------------------------------------------------
__global__ void wkv_kernel(const float* __restrict__ k,
                           const float* __restrict__ v,
                           const float* __restrict__ r,
                           const float* __restrict__ aa0,
                           const float* __restrict__ bb0,
                           const float* __restrict__ pp0,
                           const float* __restrict__ tf,
                           const float* __restrict__ td,
                           __nv_bfloat16* __restrict__ rw_hi,
                           __nv_bfloat16* __restrict__ rw_lo,
                           float* aa_out, float* bb_out, float* pp_out) {
    const int idx = blockIdx.x * blockDim.x + threadIdx.x;
    if (idx >= BC_) return;
    const int c = idx & (C_ - 1);

    float aa = aa0[idx];
    float bb = bb0[idx];
    float pp = pp0[idx];
    const float u = tf[c];
    const float w = td[c];

    const size_t base = (size_t)(idx >> 10) * (size_t)T_ * C_ + c;

#pragma unroll 4
    for (int t = 0; t < T_; t++) {
        const size_t off = base + (size_t)t * C_;
        const float kt = __ldg(k + off);
        const float vt = __ldg(v + off);
        const float rt = __ldg(r + off);

        const float ww = u + kt;
        const float qq = fmaxf(pp, ww);
        const float e1 = __expf(pp - qq);
        const float e2 = __expf(ww - qq);
        const float wkv = __fdividef(fmaf(e1, aa, e2 * vt), fmaf(e1, bb, e2));

        const float sig = __fdividef(1.0f, 1.0f + __expf(-rt));
        const float rw = sig * wkv;
        const __nv_bfloat16 h = __float2bfloat16(rw);
        rw_hi[off] = h;
        rw_lo[off] = __float2bfloat16(rw - __bfloat162float(h));

        const float ww2 = pp + w;
        const float qq2 = fmaxf(ww2, kt);
        const float e1b = __expf(ww2 - qq2);
        const float e2b = __expf(kt - qq2);
        aa = fmaf(e1b, aa, e2b * vt);
        bb = fmaf(e1b, bb, e2b);
        pp = qq2;
    }

    if (aa_out) {
        aa_out[idx] = aa;
        bb_out[idx] = bb;
        pp_out[idx] = pp;
    }
}

// ---------------------------------------------------------------------------
// Launch
// ---------------------------------------------------------------------------
extern "C" void kernel_launch(void* const* d_in, const int* in_sizes, int n_in,
                              void* d_out, int out_size) {
    const float* x   = (const float*)d_in[0];
    const float* lx  = (const float*)d_in[1];
    const float* aa0 = (const float*)d_in[2];
    const float* bb0 = (const float*)d_in[3];
    const float* pp0 = (const float*)d_in[4];
    const float* tmk = (const float*)d_in[5];
    const float* tmv = (const float*)d_in[6];
    const float* tmr = (const float*)d_in[7];
    const float* tf  = (const float*)d_in[8];
    const float* td  = (const float*)d_in[9];
    const float* Wk  = (const float*)d_in[10];
    const float* Wv  = (const float*)d_in[11];
    const float* Wr  = (const float*)d_in[12];
    const float* Wo  = (const float*)d_in[13];

    float* out = (float*)d_out;
    const bool full = (size_t)out_size >= BTC_ + 4 * (size_t)BC_;
    float* lastx_o = full ? out + BTC_ : nullptr;
    float* aa_o    = full ? out + BTC_ + 1 * (size_t)BC_ : nullptr;
    float* bb_o    = full ? out + BTC_ + 2 * (size_t)BC_ : nullptr;
    float* pp_o    = full ? out + BTC_ + 3 * (size_t)BC_ : nullptr;

    cudaFuncSetAttribute(gemm3_kernel,
                         cudaFuncAttributeMaxDynamicSharedMemorySize, SMEM_GEMM);

    __nv_bfloat16 *xkh, *xkl, *xvh, *xvl, *xrh, *xrl;
    __nv_bfloat16 *wkh, *wkl, *wvh, *wvl, *wrh, *wrl, *woh, *wol;
    float *kb, *vb, *rb;
    cudaGetSymbolAddress((void**)&xkh, g_xk_hi);
    cudaGetSymbolAddress((void**)&xkl, g_xk_lo);
    cudaGetSymbolAddress((void**)&xvh, g_xv_hi);
    cudaGetSymbolAddress((void**)&xvl, g_xv_lo);
    cudaGetSymbolAddress((void**)&xrh, g_xr_hi);
    cudaGetSymbolAddress((void**)&xrl, g_xr_lo);
    cudaGetSymbolAddress((void**)&wkh, g_wk_hi);
    cudaGetSymbolAddress((void**)&wkl, g_wk_lo);
    cudaGetSymbolAddress((void**)&wvh, g_wv_hi);
    cudaGetSymbolAddress((void**)&wvl, g_wv_lo);
    cudaGetSymbolAddress((void**)&wrh, g_wr_hi);
    cudaGetSymbolAddress((void**)&wrl, g_wr_lo);
    cudaGetSymbolAddress((void**)&woh, g_wo_hi);
    cudaGetSymbolAddress((void**)&wol, g_wo_lo);
    cudaGetSymbolAddress((void**)&kb, g_k);
    cudaGetSymbolAddress((void**)&vb, g_v);
    cudaGetSymbolAddress((void**)&rb, g_r);

    // Weight transpose + split (W[K,N] -> Wt_hi/lo[N,K])
    {
        dim3 g(C_ / 32, C_ / 32), b(32, 8);
        wt_convert_kernel<<<g, b>>>(Wk, wkh, wkl);
        wt_convert_kernel<<<g, b>>>(Wv, wvh, wvl);
        wt_convert_kernel<<<g, b>>>(Wr, wrh, wrl);
        wt_convert_kernel<<<g, b>>>(Wo, woh, wol);
    }

    // Token-shift mix -> bf16 splits (+ last_x output)
    {
        const size_t n4 = BTC_ / 4;
        const int threads = 256;
        const int blocks = (int)((n4 + threads - 1) / threads);
        mix_kernel<<<blocks, threads>>>(
            (const float4*)x, (const float4*)lx, (const float4*)tmk,
            (const float4*)tmv, (const float4*)tmr, (float4*)lastx_o);
    }

    // k, v, r projections on HMMA tensor cores
    dim3 grid(C_ / 128, M_ / 128);  // (8, 128)
    gemm3_kernel<<<grid, 256, SMEM_GEMM>>>(xkh, xkl, wkh, wkl, kb);
    gemm3_kernel<<<grid, 256, SMEM_GEMM>>>(xvh, xvl, wvh, wvl, vb);
    gemm3_kernel<<<grid, 256, SMEM_GEMM>>>(xrh, xrl, wrh, wrl, rb);

    // WKV scan + sigmoid gate -> rw hi/lo (reuses xk buffers) + state tails
    wkv_kernel<<<BC_ / 64, 64>>>(kb, vb, rb, aa0, bb0, pp0, tf, td,
                                 xkh, xkl, aa_o, bb_o, pp_o);

    // Output projection
    gemm3_kernel<<<grid, 256, SMEM_GEMM>>>(xkh, xkl, woh, wol, out);
}

// round 6
// speedup vs baseline: 4.8460x; 1.6057x over previous
#include <cuda_runtime.h>
#include <cuda_fp16.h>
#include <cstdint>
#include <cstddef>

// ---------------------------------------------------------------------------
// RWKV TimeMixing B=8,T=2048,C=1024
// GEMMs: single-pass fp16 HMMA (mma.sync.m16n8k16), fp32 accumulate.
// fp16 rounding (~2^-12/product) => norm rel-err ~3e-4, within 1e-3 budget.
// ---------------------------------------------------------------------------
constexpr int B_ = 8;
constexpr int T_ = 2048;
constexpr int C_ = 1024;
constexpr int M_ = B_ * T_;                 // 16384
constexpr size_t BTC_ = (size_t)M_ * C_;
constexpr int BC_ = B_ * C_;
constexpr int C4_ = C_ / 4;

// Scratch (device globals; runtime allocation forbidden)
__device__ __align__(16) __half g_xk[BTC_];
__device__ __align__(16) __half g_xv[BTC_];
__device__ __align__(16) __half g_xr[BTC_];
__device__ float g_k[BTC_];
__device__ float g_v[BTC_];
__device__ float g_r[BTC_];
__device__ __align__(16) __half g_wk[C_ * C_];
__device__ __align__(16) __half g_wv[C_ * C_];
__device__ __align__(16) __half g_wr[C_ * C_];
__device__ __align__(16) __half g_wo[C_ * C_];
// rw (sigmoid(r)*wkv) reuses g_xk — xk dead after the k-GEMM.

// ---------------------------------------------------------------------------
// PTX helpers
// ---------------------------------------------------------------------------
__device__ __forceinline__ uint32_t s2u(const void* p) {
    return (uint32_t)__cvta_generic_to_shared(p);
}
__device__ __forceinline__ void cp16(uint32_t s, const void* g) {
    asm volatile("cp.async.cg.shared.global [%0], [%1], 16;" :: "r"(s), "l"(g));
}
__device__ __forceinline__ void cp_commit() {
    asm volatile("cp.async.commit_group;" ::: "memory");
}
__device__ __forceinline__ void cp_wait2() {
    asm volatile("cp.async.wait_group 2;" ::: "memory");
}
__device__ __forceinline__ void ldm4(uint32_t* r, uint32_t a) {
    asm volatile("ldmatrix.sync.aligned.m8n8.x4.shared.b16 {%0,%1,%2,%3}, [%4];"
                 : "=r"(r[0]), "=r"(r[1]), "=r"(r[2]), "=r"(r[3]) : "r"(a));
}
__device__ __forceinline__ void mma16816(float* c, const uint32_t* a,
                                         uint32_t b0, uint32_t b1) {
    asm volatile(
        "mma.sync.aligned.m16n8k16.row.col.f32.f16.f16.f32 "
        "{%0,%1,%2,%3}, {%4,%5,%6,%7}, {%8,%9}, {%0,%1,%2,%3};"
        : "+f"(c[0]), "+f"(c[1]), "+f"(c[2]), "+f"(c[3])
        : "r"(a[0]), "r"(a[1]), "r"(a[2]), "r"(a[3]), "r"(b0), "r"(b1));
}

// Swizzled byte offset inside one 128x32-fp16 tile (rows of 64B, 16B chunks).
__device__ __forceinline__ uint32_t swz(int row, int chunk) {
    return (uint32_t)(row * 64 + ((chunk ^ ((row >> 1) & 3)) << 4));
}

// ---------------------------------------------------------------------------
// 1) Weight transpose + fp16: W[K,N] fp32 -> Wt[N,K] fp16
// ---------------------------------------------------------------------------
__global__ void wt_convert_kernel(const float* __restrict__ W,
                                  __half* __restrict__ o) {
    __shared__ float tile[32][33];
    const int n0 = blockIdx.x * 32, k0 = blockIdx.y * 32;
    const int tx = threadIdx.x, ty = threadIdx.y;
    for (int i = ty; i < 32; i += 8)
        tile[i][tx] = W[(size_t)(k0 + i) * C_ + n0 + tx];
    __syncthreads();
    for (int i = ty; i < 32; i += 8)
        o[(size_t)(n0 + i) * C_ + k0 + tx] = __float2half(tile[tx][i]);
}

// ---------------------------------------------------------------------------
// 2) Token-shift + time-mix -> fp16 operands; also last_x output
// ---------------------------------------------------------------------------
__device__ __forceinline__ float4 mix4(float4 a, float4 xx, float4 m) {
    float4 r;
    r.x = fmaf(m.x, a.x - xx.x, xx.x);
    r.y = fmaf(m.y, a.y - xx.y, xx.y);
    r.z = fmaf(m.z, a.z - xx.z, xx.z);
    r.w = fmaf(m.w, a.w - xx.w, xx.w);
    return r;
}
__device__ __forceinline__ void st_h4(float4 v, __half* p, size_t e) {
    __half2 h0, h1;
    h0.x = __float2half(v.x); h0.y = __float2half(v.y);
    h1.x = __float2half(v.z); h1.y = __float2half(v.w);
    *reinterpret_cast<__half2*>(p + e) = h0;
    *reinterpret_cast<__half2*>(p + e + 2) = h1;
}

__global__ void mix_kernel(const float4* __restrict__ x,
                           const float4* __restrict__ last_x,
                           const float4* __restrict__ tmk,
                           const float4* __restrict__ tmv,
                           const float4* __restrict__ tmr,
                           float4* lastx_out) {
    size_t i = (size_t)blockIdx.x * blockDim.x + threadIdx.x;
    if (i >= BTC_ / 4) return;
    int c4 = (int)(i % C4_);
    size_t bt = i / C4_;
    int t = (int)(bt % T_);
    int b = (int)(bt / T_);

    float4 xc = x[i];
    float4 xx = (t == 0) ? last_x[(size_t)b * C4_ + c4] : x[i - C4_];
    size_t e = i * 4;
    st_h4(mix4(xc, xx, tmk[c4]), g_xk, e);
    st_h4(mix4(xc, xx, tmv[c4]), g_xv, e);
    st_h4(mix4(xc, xx, tmr[c4]), g_xr, e);

    if (t == T_ - 1 && lastx_out) lastx_out[(size_t)b * C4_ + c4] = xc;
}

// ---------------------------------------------------------------------------
// 3) HMMA GEMM: C[M,N] = A @ Wt^T, fp16 single pass, fp32 out.
//    CTA 128x128x32, 8 warps (warp tile 32x64), 4-stage cp.async pipeline.
// ---------------------------------------------------------------------------
constexpr int BK_ = 32;
constexpr int KSTAGES = C_ / BK_;           // 32
constexpr int TILE_BYTES = 128 * BK_ * 2;   // 8192 per operand tile
constexpr int STAGE_BYTES = 2 * TILE_BYTES; // 16384 (A, B)
constexpr int NSTG = 4;
constexpr int SMEM_GEMM = NSTG * STAGE_BYTES;  // 65536

__global__ __launch_bounds__(256, 2)
void gemm_kernel(const __half* __restrict__ A, const __half* __restrict__ Bm,
                 float* __restrict__ Cout) {
    extern __shared__ char smem[];
    const uint32_t sbase = s2u(smem);
    const int tid = threadIdx.x;
    const int lane = tid & 31;
    const int wid = tid >> 5;
    const int wm = wid >> 1;   // 0..3  (m offset 32*wm)
    const int wn = wid & 1;    // 0..1  (n offset 64*wn)
    const int bm = blockIdx.y * 128, bn = blockIdx.x * 128;

    const char* aG = (const char*)A + (size_t)bm * 2048;
    const char* bG = (const char*)Bm + (size_t)bn * 2048;

    auto load_stage = [&](int s) {
        const uint32_t sb = sbase + (s % NSTG) * STAGE_BYTES;
        const int kbyte = s * 64;
#pragma unroll
        for (int i = 0; i < 2; i++) {
            const int idx = tid + i * 256;  // 0..511
            const int row = idx >> 2;
            const int ch = idx & 3;
            const uint32_t so = swz(row, ch);
            const size_t go = (size_t)row * 2048 + kbyte + ch * 16;
            cp16(sb + so, aG + go);
            cp16(sb + TILE_BYTES + so, bG + go);
        }
        cp_commit();
    };

    float acc[2][8][4];
#pragma unroll
    for (int mt = 0; mt < 2; mt++)
#pragma unroll
        for (int nt = 0; nt < 8; nt++)
#pragma unroll
            for (int i = 0; i < 4; i++) acc[mt][nt][i] = 0.0f;

    load_stage(0);
    load_stage(1);
    load_stage(2);

    for (int s = 0; s < KSTAGES; s++) {
        cp_wait2();
        __syncthreads();
        if (s + 3 < KSTAGES) load_stage(s + 3);

        const uint32_t sb = sbase + (s % NSTG) * STAGE_BYTES;
#pragma unroll
        for (int ks = 0; ks < 2; ks++) {
            const int lrow = lane & 15;
            const int lch = ks * 2 + (lane >> 4);
            uint32_t af[2][4], bf[4][4];
#pragma unroll
            for (int mt = 0; mt < 2; mt++)
                ldm4(af[mt], sb + swz(wm * 32 + mt * 16 + lrow, lch));
#pragma unroll
            for (int p = 0; p < 4; p++)
                ldm4(bf[p], sb + TILE_BYTES + swz(wn * 64 + p * 16 + lrow, lch));
#pragma unroll
            for (int mt = 0; mt < 2; mt++)
#pragma unroll
                for (int p = 0; p < 4; p++) {
                    mma16816(acc[mt][2 * p], af[mt], bf[p][0], bf[p][2]);
                    mma16816(acc[mt][2 * p + 1], af[mt], bf[p][1], bf[p][3]);
                }
        }
    }

    // Epilogue: direct fp32 stores
#pragma unroll
    for (int mt = 0; mt < 2; mt++) {
        const int row0 = bm + wm * 32 + mt * 16 + (lane >> 2);
#pragma unroll
        for (int nt = 0; nt < 8; nt++) {
            const int col = bn + wn * 64 + nt * 8 + (lane & 3) * 2;
            float* c = acc[mt][nt];
            *reinterpret_cast<float2*>(Cout + (size_t)row0 * C_ + col) =
                make_float2(c[0], c[1]);
            *reinterpret_cast<float2*>(Cout + (size_t)(row0 + 8) * C_ + col) =
                make_float2(c[2], c[3]);
        }
    }
}

// ---------------------------------------------------------------------------
// 4) WKV serial scan + sigmoid gate -> rw fp16 (+ state outputs)
//    In each (e1,e2) pair one factor is exp(0)=1 -> single MUFU per pair.
// ---------------------------------------------------------------------------
__global__ void wkv_kernel(const float* __restrict__ k,
                           const float* __restrict__ v,
                           const float* __restrict__ r,
                           const float* __restrict__ aa0,
                           const float* __restrict__ bb0,
                           const float* __restrict__ pp0,
                           const float* __restrict__ tf,
                           const float* __restrict__ td,
                           __half* __restrict__ rw,
                           float* aa_out, float* bb_out, float* pp_out) {
    const int idx = blockIdx.x * blockDim.x + threadIdx.x;
    if (idx >= BC_) return;
    const int c = idx & (C_ - 1);

    float aa = aa0[idx];
    float bb = bb0[idx];
    float pp = pp0[idx];
    const float u = tf[c];
    const float w = td[c];

    const size_t base = (size_t)(idx >> 10) * (size_t)T_ * C_ + c;

#pragma unroll 4
    for (int t = 0; t < T_; t++) {
        const size_t off = base + (size_t)t * C_;
        const float kt = __ldg(k + off);
        const float vt = __ldg(v + off);
        const float rt = __ldg(r + off);

        // wkv = (e1*aa + e2*vt)/(e1*bb + e2), e1=exp(pp-qq), e2=exp(ww-qq)
        const float ww = u + kt;
        const float d = pp - ww;
        const float ed = __expf(-fabsf(d));
        const float e1 = (d >= 0.0f) ? 1.0f : ed;
        const float e2 = (d >= 0.0f) ? ed : 1.0f;
        const float wkv = __fdividef(fmaf(e1, aa, e2 * vt), fmaf(e1, bb, e2));

        const float sig = __fdividef(1.0f, 1.0f + __expf(-rt));
        rw[off] = __float2half(sig * wkv);

        // state update
        const float ww2 = pp + w;
        const float d2 = ww2 - kt;
        const float ed2 = __expf(-fabsf(d2));
        const float e1b = (d2 >= 0.0f) ? 1.0f : ed2;
        const float e2b = (d2 >= 0.0f) ? ed2 : 1.0f;
        aa = fmaf(e1b, aa, e2b * vt);
        bb = fmaf(e1b, bb, e2b);
        pp = (d2 >= 0.0f) ? ww2 : kt;
    }

    if (aa_out) {
        aa_out[idx] = aa;
        bb_out[idx] = bb;
        pp_out[idx] = pp;
    }
}

// ---------------------------------------------------------------------------
// Launch
// ---------------------------------------------------------------------------
extern "C" void kernel_launch(void* const* d_in, const int* in_sizes, int n_in,
                              void* d_out, int out_size) {
    const float* x   = (const float*)d_in[0];
    const float* lx  = (const float*)d_in[1];
    const float* aa0 = (const float*)d_in[2];
    const float* bb0 = (const float*)d_in[3];
    const float* pp0 = (const float*)d_in[4];
    const float* tmk = (const float*)d_in[5];
    const float* tmv = (const float*)d_in[6];
    const float* tmr = (const float*)d_in[7];
    const float* tf  = (const float*)d_in[8];
    const float* td  = (const float*)d_in[9];
    const float* Wk  = (const float*)d_in[10];
    const float* Wv  = (const float*)d_in[11];
    const float* Wr  = (const float*)d_in[12];
    const float* Wo  = (const float*)d_in[13];

    float* out = (float*)d_out;
    const bool full = (size_t)out_size >= BTC_ + 4 * (size_t)BC_;
    float* lastx_o = full ? out + BTC_ : nullptr;
    float* aa_o    = full ? out + BTC_ + 1 * (size_t)BC_ : nullptr;
    float* bb_o    = full ? out + BTC_ + 2 * (size_t)BC_ : nullptr;
    float* pp_o    = full ? out + BTC_ + 3 * (size_t)BC_ : nullptr;

    cudaFuncSetAttribute(gemm_kernel,
                         cudaFuncAttributeMaxDynamicSharedMemorySize, SMEM_GEMM);

    __half *xk, *xv, *xr, *wk, *wv, *wr, *wo;
    float *kb, *vb, *rb;
    cudaGetSymbolAddress((void**)&xk, g_xk);
    cudaGetSymbolAddress((void**)&xv, g_xv);
    cudaGetSymbolAddress((void**)&xr, g_xr);
    cudaGetSymbolAddress((void**)&wk, g_wk);
    cudaGetSymbolAddress((void**)&wv, g_wv);
    cudaGetSymbolAddress((void**)&wr, g_wr);
    cudaGetSymbolAddress((void**)&wo, g_wo);
    cudaGetSymbolAddress((void**)&kb, g_k);
    cudaGetSymbolAddress((void**)&vb, g_v);
    cudaGetSymbolAddress((void**)&rb, g_r);

    // Weight transpose + fp16 (W[K,N] -> Wt[N,K])
    {
        dim3 g(C_ / 32, C_ / 32), b(32, 8);
        wt_convert_kernel<<<g, b>>>(Wk, wk);
        wt_convert_kernel<<<g, b>>>(Wv, wv);
        wt_convert_kernel<<<g, b>>>(Wr, wr);
        wt_convert_kernel<<<g, b>>>(Wo, wo);
    }

    // Token-shift mix -> fp16 (+ last_x output)
    {
        const size_t n4 = BTC_ / 4;
        const int threads = 256;
        const int blocks = (int)((n4 + threads - 1) / threads);
        mix_kernel<<<blocks, threads>>>(
            (const float4*)x, (const float4*)lx, (const float4*)tmk,
            (const float4*)tmv, (const float4*)tmr, (float4*)lastx_o);
    }

    // k, v, r projections
    dim3 grid(C_ / 128, M_ / 128);  // (8, 128)
    gemm_kernel<<<grid, 256, SMEM_GEMM>>>(xk, wk, kb);
    gemm_kernel<<<grid, 256, SMEM_GEMM>>>(xv, wv, vb);
    gemm_kernel<<<grid, 256, SMEM_GEMM>>>(xr, wr, rb);

    // WKV scan + sigmoid gate -> rw fp16 (reuses xk buffer) + state tails
    wkv_kernel<<<BC_ / 32, 32>>>(kb, vb, rb, aa0, bb0, pp0, tf, td,
                                 xk, aa_o, bb_o, pp_o);

    // Output projection
    gemm_kernel<<<grid, 256, SMEM_GEMM>>>(xk, wo, out);
}